// round 4
// baseline (speedup 1.0000x reference)
#include <cuda_runtime.h>
#include <cuda_bf16.h>

// LayerNorm over last dim W=256 for (8,128,128,256) fp32 + per-channel affine.
// R1 shape (1 warp per row, 2x LDG.128, shuffle-tree reduce) -- best measured.
// Delta vs R1: evict-streaming stores (__stcs), hoisted gain/bias, balanced
// FADD trees.

#define EPS 1e-8f
#define W_DIM 256
#define C_DIM 128

__global__ __launch_bounds__(256, 8)
void ln_warp_kernel(const float* __restrict__ inp,
                    const float* __restrict__ gain,
                    const float* __restrict__ bias,
                    float* __restrict__ out,
                    int n_rows)
{
    const int warp_in_block = threadIdx.x >> 5;
    const int lane = threadIdx.x & 31;
    const int row = blockIdx.x * 8 + warp_in_block;
    if (row >= n_rows) return;

    // Hoist affine params (independent loads, overlap with bulk-load latency).
    const int c = (row >> 7) & (C_DIM - 1);   // row = ((b*C+c)*H + h), H=128
    const float g = __ldg(gain + c);
    const float b = __ldg(bias + c);

    const float4* in4 = reinterpret_cast<const float4*>(inp) + (size_t)row * 64;
    float4*      out4 = reinterpret_cast<float4*>(out)       + (size_t)row * 64;

    float4 v0 = in4[lane * 2 + 0];
    float4 v1 = in4[lane * 2 + 1];

    // Balanced 3-level adder trees.
    float s  = ((v0.x + v0.y) + (v0.z + v0.w)) + ((v1.x + v1.y) + (v1.z + v1.w));
    float ss = ((v0.x*v0.x + v0.y*v0.y) + (v0.z*v0.z + v0.w*v0.w))
             + ((v1.x*v1.x + v1.y*v1.y) + (v1.z*v1.z + v1.w*v1.w));

    // Warp reduce (two independent chains pipeline through SHFL).
    #pragma unroll
    for (int off = 16; off > 0; off >>= 1) {
        s  += __shfl_xor_sync(0xFFFFFFFFu, s,  off);
        ss += __shfl_xor_sync(0xFFFFFFFFu, ss, off);
    }

    const float inv_w = 1.0f / (float)W_DIM;
    float mean = s * inv_w;
    float var  = ss * inv_w - mean * mean;
    float rstd = rsqrtf(var + EPS);

    float scale = rstd * g;
    float shift = b - mean * scale;

    v0.x = v0.x * scale + shift;  v0.y = v0.y * scale + shift;
    v0.z = v0.z * scale + shift;  v0.w = v0.w * scale + shift;
    v1.x = v1.x * scale + shift;  v1.y = v1.y * scale + shift;
    v1.z = v1.z * scale + shift;  v1.w = v1.w * scale + shift;

    // Evict-streaming stores: output is never re-read, skip L2 write-allocate
    // retention.
    __stcs(&out4[lane * 2 + 0], v0);
    __stcs(&out4[lane * 2 + 1], v1);
}

extern "C" void kernel_launch(void* const* d_in, const int* in_sizes, int n_in,
                              void* d_out, int out_size) {
    const float* inp  = (const float*)d_in[0];
    const float* gain = (const float*)d_in[1];
    const float* bias = (const float*)d_in[2];
    float* out = (float*)d_out;

    int n_rows = in_sizes[0] / W_DIM;   // 131072
    int blocks = (n_rows + 7) / 8;      // 16384

    ln_warp_kernel<<<blocks, 256>>>(inp, gain, bias, out, n_rows);
}